// round 9
// baseline (speedup 1.0000x reference)
#include <cuda_runtime.h>
#include <stdint.h>

// Problem constants (SHAPE = (16,1,1024,1024), RATIO = 0.25)
#define N_TOTAL   16777216
#define N_VEC     (N_TOTAL / 4)
#define K_SEL     4194304u
#define GRID_BIG  304
#define TPB       1024
#define FULL      0xFFFFFFFFu
#define NSEG      (GRID_BIG * 32)   // 9728 warp-private segments
#define SEG_CAP   1792              // hard upper bound per warp segment
#define HBINS     8192              // sample histogram bins = bits[30:18]
#define H2BINS    32768             // refinement histogram: window bits [b:b-14]
#define S_BLOCKS  128               // 128*1024 = 131072 samples
#define R_HI      30848u            // sample-rank (from top) for T_hi (K_s - 12sigma)
#define R_LO      34688u            // sample-rank for T_lo (K_s + 12sigma)

// Device-global state (statically zero-initialized)
__device__ __align__(16) uint32_t g_hist[HBINS];
__device__ __align__(16) uint32_t g_h2[H2BINS];
__device__ uint32_t g_scratch2[NSEG * SEG_CAP];  // compacted window elements
__device__ uint32_t g_wcnt[NSEG];                // per-segment counts
__device__ uint32_t g_Tlo, g_Thi;
__device__ uint32_t g_cntAbove;                  // # elements >= T_hi
__device__ double   g_sum;                       // exact sum of elements >= T_hi

// ---------------------------------------------------------------------------
__device__ __forceinline__ float bce_loss(float x, float t) {
    // max(x,0) - x*t + log1p(exp(-|x|)); always >= 0 for t in [0,1)
    float e = __expf(-fabsf(x));
    float l = fmaxf(x, 0.0f) - x * t + __logf(1.0f + e);
    return fmaxf(l, 0.0f);   // keep sign bit 0 -> uint order == float order
}

// b = highest bit where window values can differ (clamped >= 14).
// All window v share bits [31:b+1] == pfx0; histogram indexes bits [b:b-14].
__device__ __forceinline__ void win_params(uint32_t Tlo, uint32_t Thi,
                                           uint32_t& pfx0, int& s3) {
    uint32_t m = Tlo ^ (Thi - 1u);
    int b = m ? (31 - __clz((int)m)) : 14;
    if (b < 14) b = 14;
    s3 = b - 14;                       // 0 -> bins are exact bit patterns
    pfx0 = Tlo >> (b + 1);
}

// ---------------------------------------------------------------------------
// ksample: zero g_h2 for this replay; BCE on first 131072 elements ->
// 8192-bin coarse histogram of bits[30:18].
// ---------------------------------------------------------------------------
__global__ void __launch_bounds__(TPB) ksample(const float* __restrict__ pred,
                                               const float* __restrict__ tgt) {
    __shared__ uint32_t sh[HBINS];
    const int t = threadIdx.x;
    int gidx = blockIdx.x * TPB + t;
    if (gidx < H2BINS) g_h2[gidx] = 0u;            // 128K threads >= 32K bins
    for (int i = t; i < HBINS; i += TPB) sh[i] = 0u;
    __syncthreads();

    float l = bce_loss(pred[gidx], tgt[gidx]);     // one sample per thread
    atomicAdd(&sh[__float_as_uint(l) >> 18], 1u);
    __syncthreads();
    for (int i = t; i < HBINS; i += TPB) {
        uint32_t c = sh[i];
        if (c) atomicAdd(&g_hist[i], c);
    }
}

// ---------------------------------------------------------------------------
// kmain: (A) every block derives [T_lo,T_hi) from the sample histogram;
// (B) single full pass: exact sum/count of v>=T_hi, compact window elements
// into warp-private segments (zero atomics in the hot loop).
// ---------------------------------------------------------------------------
__global__ void __launch_bounds__(TPB) kmain(const float* __restrict__ pred,
                                             const float* __restrict__ tgt) {
    __shared__ uint32_t sscan[TPB];
    __shared__ uint32_t s_Tlo, s_Thi;
    __shared__ float    wp[32];
    __shared__ uint32_t wc[32];
    const int t = threadIdx.x;

    // --- Phase A: window selection (redundant per block) ---
    uint4 h0 = ((const uint4*)g_hist)[t * 2];
    uint4 h1 = ((const uint4*)g_hist)[t * 2 + 1];
    uint32_t hb[8] = {h0.x, h0.y, h0.z, h0.w, h1.x, h1.y, h1.z, h1.w};
    uint32_t part = 0;
#pragma unroll
    for (int j = 0; j < 8; j++) part += hb[j];
    sscan[t] = part;
    __syncthreads();
    for (int off = 1; off < TPB; off <<= 1) {       // inclusive suffix scan
        uint32_t v = (t + off < TPB) ? sscan[t + off] : 0u;
        __syncthreads();
        sscan[t] += v;
        __syncthreads();
    }
    uint32_t tail = sscan[t] - part;                // strictly-above count
    for (int j = 7; j >= 0; j--) {                  // bins high -> low
        uint32_t C = tail, h = hb[j];
        if (C < R_HI && C + h >= R_HI) s_Thi = ((uint32_t)(t * 8 + j) + 1u) << 18;
        if (C < R_LO && C + h >= R_LO) s_Tlo = ((uint32_t)(t * 8 + j)) << 18;
        tail += h;
    }
    __syncthreads();
    const uint32_t Tlo = s_Tlo, Thi = s_Thi;
    if (blockIdx.x == 0 && t == 0) { g_Tlo = Tlo; g_Thi = Thi; }

    // --- Phase B: main pass (identical structure to the 63.6us version) ---
    const uint32_t lane = t & 31u;
    const uint32_t lt   = (1u << lane) - 1u;
    const uint32_t seg  = blockIdx.x * 32u + (t >> 5);
    uint32_t wbase = seg * SEG_CAP;
    const uint32_t wstart = wbase;
    float fs = 0.0f;
    uint32_t ch = 0;

    int tid = blockIdx.x * TPB + t;
    const int stride = GRID_BIG * TPB;
    const float4* p4 = (const float4*)pred;
    const float4* t4 = (const float4*)tgt;

#define KM_PROC(PX, TX) do {                                          \
        uint32_t _v = __float_as_uint(bce_loss((PX), (TX)));          \
        bool _hi = _v >= Thi;                                         \
        if (_hi) { fs += __uint_as_float(_v); ch++; }                 \
        bool _w = (_v >= Tlo) && !_hi;                                \
        unsigned _mm = __ballot_sync(FULL, _w);                       \
        if (_w) g_scratch2[wbase + __popc(_mm & lt)] = _v;            \
        wbase += __popc(_mm);                                         \
    } while (0)

    for (int i = tid; i < N_VEC; i += 2 * stride) {   // warp-uniform guards
        float4 pa = p4[i], ta = t4[i];
        bool sec = (i + stride) < N_VEC;
        float4 pb, tb;
        if (sec) { pb = p4[i + stride]; tb = t4[i + stride]; }
        KM_PROC(pa.x, ta.x); KM_PROC(pa.y, ta.y);
        KM_PROC(pa.z, ta.z); KM_PROC(pa.w, ta.w);
        if (sec) {
            KM_PROC(pb.x, tb.x); KM_PROC(pb.y, tb.y);
            KM_PROC(pb.z, tb.z); KM_PROC(pb.w, tb.w);
        }
    }
#undef KM_PROC

    if (lane == 0) g_wcnt[seg] = wbase - wstart;
#pragma unroll
    for (int o = 16; o; o >>= 1) {
        fs += __shfl_down_sync(FULL, fs, o);
        ch += __shfl_down_sync(FULL, ch, o);
    }
    if (lane == 0) { wp[t >> 5] = fs; wc[t >> 5] = ch; }
    __syncthreads();
    if (t == 0) {
        double d = 0.0; uint32_t c = 0;
#pragma unroll
        for (int i = 0; i < 32; i++) { d += (double)wp[i]; c += wc[i]; }
        atomicAdd(&g_sum, d);
        atomicAdd(&g_cntAbove, c);
    }
}

// ---------------------------------------------------------------------------
// krefine: histogram the compacted window elements (~490K) into 32768 bins
// using bits [b:b-14] (known from the window). One warp per segment.
// ---------------------------------------------------------------------------
__global__ void __launch_bounds__(TPB) krefine() {
    uint32_t pfx0; int s3; win_params(g_Tlo, g_Thi, pfx0, s3);
    const uint32_t lane = threadIdx.x & 31u;
    const uint32_t seg  = blockIdx.x * 32u + (threadIdx.x >> 5);
    const uint32_t n    = g_wcnt[seg];
    const uint32_t base = seg * SEG_CAP;
    for (uint32_t j = lane; j < n; j += 32) {
        uint32_t v = g_scratch2[base + j];
        atomicAdd(&g_h2[(v >> s3) & (H2BINS - 1)], 1u);
    }
}

// ---------------------------------------------------------------------------
// kfin: one block. Descending scan of the 32768-bin histogram -> exact
// crossing bin + tie count; sum count*binValue above; write mean; re-zero
// g_hist + scalars for the next graph replay (g_h2 is zeroed by ksample).
// ---------------------------------------------------------------------------
__global__ void __launch_bounds__(TPB) kfin(float* __restrict__ out) {
    __shared__ uint32_t sscan[TPB];
    __shared__ double   dp[32];
    __shared__ uint32_t s_B, s_need;
    const int t = threadIdx.x;
    uint32_t pfx0; int s3; win_params(g_Tlo, g_Thi, pfx0, s3);
    const uint32_t kr = K_SEL - g_cntAbove;    // needed from the window

    // Each thread owns 32 contiguous bins.
    uint32_t hb[32];
#pragma unroll
    for (int q = 0; q < 8; q++) {
        uint4 h = ((const uint4*)g_h2)[t * 8 + q];
        hb[q * 4] = h.x; hb[q * 4 + 1] = h.y; hb[q * 4 + 2] = h.z; hb[q * 4 + 3] = h.w;
    }
    uint32_t part = 0;
#pragma unroll
    for (int j = 0; j < 32; j++) part += hb[j];
    sscan[t] = part;
    __syncthreads();
    for (int off = 1; off < TPB; off <<= 1) {       // inclusive suffix scan
        uint32_t v = (t + off < TPB) ? sscan[t + off] : 0u;
        __syncthreads();
        sscan[t] += v;
        __syncthreads();
    }
    uint32_t tail = sscan[t] - part;                // count in chunks above t
    {
        uint32_t C = tail;
        for (int j = 31; j >= 0; j--) {             // bins high -> low
            uint32_t h = hb[j];
            if (C < kr && C + h >= kr) { s_B = (uint32_t)(t * 32 + j); s_need = kr - C; }
            C += h;
        }
    }
    __syncthreads();
    const uint32_t B = s_B, need = s_need;

    // Contributions: full bins above B, plus `need` elements at bin B.
    double ds = 0.0;
    for (int j = 0; j < 32; j++) {
        uint32_t idx = (uint32_t)(t * 32 + j);
        uint32_t h = hb[j];
        if ((idx > B && h) || idx == B) {
            uint32_t bits = (((pfx0 << 15) | idx) << s3) |
                            (s3 ? (1u << (s3 - 1)) : 0u);   // midpoint (exact if s3==0)
            double m = (double)__uint_as_float(bits);
            ds += (idx > B) ? (double)h * m : (double)need * m;
        }
    }
    const uint32_t lane = t & 31u;
#pragma unroll
    for (int o = 16; o; o >>= 1) ds += __shfl_down_sync(FULL, ds, o);
    if (lane == 0) dp[t >> 5] = ds;
    __syncthreads();
    if (t == 0) {
        double tot = g_sum;
#pragma unroll
        for (int i = 0; i < 32; i++) tot += dp[i];
        out[0] = (float)(tot / (double)K_SEL);
    }
    __syncthreads();
    // Re-zero remaining state for the next graph replay.
    for (int i = t; i < HBINS; i += TPB) g_hist[i] = 0u;
    if (t == 0) { g_sum = 0.0; g_cntAbove = 0u; }
}

// ---------------------------------------------------------------------------
extern "C" void kernel_launch(void* const* d_in, const int* in_sizes, int n_in,
                              void* d_out, int out_size) {
    (void)in_sizes; (void)n_in; (void)out_size;
    const float* pred = (const float*)d_in[0];
    const float* tgt  = (const float*)d_in[1];
    float* out = (float*)d_out;

    ksample<<<S_BLOCKS, TPB>>>(pred, tgt);
    kmain<<<GRID_BIG, TPB>>>(pred, tgt);
    krefine<<<GRID_BIG, TPB>>>();
    kfin<<<1, TPB>>>(out);
}

// round 10
// speedup vs baseline: 1.4186x; 1.4186x over previous
#include <cuda_runtime.h>
#include <stdint.h>

// Problem constants (SHAPE = (16,1,1024,1024), RATIO = 0.25)
#define N_TOTAL   16777216
#define N_VEC     (N_TOTAL / 4)
#define K_SEL     4194304u
#define GRID_BIG  304
#define TPB       1024
#define FULL      0xFFFFFFFFu
#define NSEG      (GRID_BIG * 32)   // 9728 warp-private segments
#define SEG_CAP   1792              // hard upper bound per warp segment
#define HBINS     8192              // sample histogram bins = bits[30:18]
#define H2BINS    4096              // refinement histogram: window bits [b:b-11]
#define S_BLOCKS  128               // 128*1024 = 131072 samples
#define R_HI      30848u            // sample-rank (from top) for T_hi (K_s - 12sigma)
#define R_LO      34688u            // sample-rank for T_lo (K_s + 12sigma)

// Device-global state (statically zero-initialized)
__device__ __align__(16) uint32_t g_hist[HBINS];
__device__ __align__(16) uint32_t g_h2[H2BINS];
__device__ uint32_t g_scratch2[NSEG * SEG_CAP];  // compacted window elements
__device__ uint32_t g_Tlo, g_Thi;
__device__ uint32_t g_cntAbove;                  // # elements >= T_hi
__device__ double   g_sum;                       // exact sum of elements >= T_hi

// ---------------------------------------------------------------------------
__device__ __forceinline__ float bce_loss(float x, float t) {
    // max(x,0) - x*t + log1p(exp(-|x|)); always >= 0 for t in [0,1)
    float e = __expf(-fabsf(x));
    float l = fmaxf(x, 0.0f) - x * t + __logf(1.0f + e);
    return fmaxf(l, 0.0f);   // keep sign bit 0 -> uint order == float order
}

// b = highest bit where window values can differ (clamped >= 11).
// All window v share bits [31:b+1] == pfx0; histogram indexes bits [b:b-11].
__device__ __forceinline__ void win_params(uint32_t Tlo, uint32_t Thi,
                                           uint32_t& pfx0, int& s3) {
    uint32_t m = Tlo ^ (Thi - 1u);
    int b = m ? (31 - __clz((int)m)) : 11;
    if (b < 11) b = 11;
    s3 = b - 11;                       // bin width = 2^s3 ulps
    pfx0 = Tlo >> (b + 1);
}

// ---------------------------------------------------------------------------
// ksample: zero g_h2 for this replay; BCE on first 131072 elements ->
// 8192-bin coarse histogram of bits[30:18].
// ---------------------------------------------------------------------------
__global__ void __launch_bounds__(TPB) ksample(const float* __restrict__ pred,
                                               const float* __restrict__ tgt) {
    __shared__ uint32_t sh[HBINS];
    const int t = threadIdx.x;
    int gidx = blockIdx.x * TPB + t;
    if (gidx < H2BINS) g_h2[gidx] = 0u;            // 128K threads >= 4K bins
    for (int i = t; i < HBINS; i += TPB) sh[i] = 0u;
    __syncthreads();

    float l = bce_loss(pred[gidx], tgt[gidx]);     // one sample per thread
    atomicAdd(&sh[__float_as_uint(l) >> 18], 1u);
    __syncthreads();
    for (int i = t; i < HBINS; i += TPB) {
        uint32_t c = sh[i];
        if (c) atomicAdd(&g_hist[i], c);
    }
}

// ---------------------------------------------------------------------------
// kmain: (A) every block derives [T_lo,T_hi) from the sample histogram;
// (B) single full pass: exact sum/count of v>=T_hi, compact window elements
// into warp-private segments (zero atomics in the hot loop);
// (C) tail: each warp histograms its own (L2-hot) segment into g_h2.
// ---------------------------------------------------------------------------
__global__ void __launch_bounds__(TPB) kmain(const float* __restrict__ pred,
                                             const float* __restrict__ tgt) {
    __shared__ uint32_t sscan[TPB];
    __shared__ uint32_t s_Tlo, s_Thi;
    __shared__ float    wp[32];
    __shared__ uint32_t wc[32];
    const int t = threadIdx.x;

    // --- Phase A: window selection (redundant per block) ---
    uint4 h0 = ((const uint4*)g_hist)[t * 2];
    uint4 h1 = ((const uint4*)g_hist)[t * 2 + 1];
    uint32_t hb[8] = {h0.x, h0.y, h0.z, h0.w, h1.x, h1.y, h1.z, h1.w};
    uint32_t part = 0;
#pragma unroll
    for (int j = 0; j < 8; j++) part += hb[j];
    sscan[t] = part;
    __syncthreads();
    for (int off = 1; off < TPB; off <<= 1) {       // inclusive suffix scan
        uint32_t v = (t + off < TPB) ? sscan[t + off] : 0u;
        __syncthreads();
        sscan[t] += v;
        __syncthreads();
    }
    uint32_t tail = sscan[t] - part;                // strictly-above count
    for (int j = 7; j >= 0; j--) {                  // bins high -> low
        uint32_t C = tail, h = hb[j];
        if (C < R_HI && C + h >= R_HI) s_Thi = ((uint32_t)(t * 8 + j) + 1u) << 18;
        if (C < R_LO && C + h >= R_LO) s_Tlo = ((uint32_t)(t * 8 + j)) << 18;
        tail += h;
    }
    __syncthreads();
    const uint32_t Tlo = s_Tlo, Thi = s_Thi;
    if (blockIdx.x == 0 && t == 0) { g_Tlo = Tlo; g_Thi = Thi; }

    // --- Phase B: main pass (hot loop identical to the 63.6us version) ---
    const uint32_t lane = t & 31u;
    const uint32_t lt   = (1u << lane) - 1u;
    const uint32_t seg  = blockIdx.x * 32u + (t >> 5);
    uint32_t wbase = seg * SEG_CAP;
    const uint32_t wstart = wbase;
    float fs = 0.0f;
    uint32_t ch = 0;

    int tid = blockIdx.x * TPB + t;
    const int stride = GRID_BIG * TPB;
    const float4* p4 = (const float4*)pred;
    const float4* t4 = (const float4*)tgt;

#define KM_PROC(PX, TX) do {                                          \
        uint32_t _v = __float_as_uint(bce_loss((PX), (TX)));          \
        bool _hi = _v >= Thi;                                         \
        if (_hi) { fs += __uint_as_float(_v); ch++; }                 \
        bool _w = (_v >= Tlo) && !_hi;                                \
        unsigned _mm = __ballot_sync(FULL, _w);                       \
        if (_w) g_scratch2[wbase + __popc(_mm & lt)] = _v;            \
        wbase += __popc(_mm);                                         \
    } while (0)

    for (int i = tid; i < N_VEC; i += 2 * stride) {   // warp-uniform guards
        float4 pa = p4[i], ta = t4[i];
        bool sec = (i + stride) < N_VEC;
        float4 pb, tb;
        if (sec) { pb = p4[i + stride]; tb = t4[i + stride]; }
        KM_PROC(pa.x, ta.x); KM_PROC(pa.y, ta.y);
        KM_PROC(pa.z, ta.z); KM_PROC(pa.w, ta.w);
        if (sec) {
            KM_PROC(pb.x, tb.x); KM_PROC(pb.y, tb.y);
            KM_PROC(pb.z, tb.z); KM_PROC(pb.w, tb.w);
        }
    }
#undef KM_PROC

    // Block-reduce the exact sum/count of v >= T_hi.
#pragma unroll
    for (int o = 16; o; o >>= 1) {
        fs += __shfl_down_sync(FULL, fs, o);
        ch += __shfl_down_sync(FULL, ch, o);
    }
    if (lane == 0) { wp[t >> 5] = fs; wc[t >> 5] = ch; }
    __syncthreads();
    if (t == 0) {
        double d = 0.0; uint32_t c = 0;
#pragma unroll
        for (int i = 0; i < 32; i++) { d += (double)wp[i]; c += wc[i]; }
        atomicAdd(&g_sum, d);
        atomicAdd(&g_cntAbove, c);
    }

    // --- Phase C: histogram own segment (L2-hot) into g_h2 ---
    uint32_t pfx0; int s3; win_params(Tlo, Thi, pfx0, s3);
    __threadfence_block();                 // order own-warp stores before loads
    __syncwarp();
    const uint32_t nw = wbase - wstart;
    for (uint32_t j = lane; j < nw; j += 32) {
        uint32_t v = g_scratch2[wstart + j];
        atomicAdd(&g_h2[(v >> s3) & (H2BINS - 1)], 1u);
    }
}

// ---------------------------------------------------------------------------
// kfin: one block, coalesced. uint4 per thread covers all 4096 bins.
// Descending scan -> crossing bin + tie count; weighted midpoint sum above;
// write mean; re-zero g_hist + scalars (g_h2 re-zeroed by next ksample).
// ---------------------------------------------------------------------------
__global__ void __launch_bounds__(TPB) kfin(float* __restrict__ out) {
    __shared__ uint32_t sscan[TPB];
    __shared__ double   dp[32];
    __shared__ uint32_t s_B, s_need;
    const int t = threadIdx.x;
    uint32_t pfx0; int s3; win_params(g_Tlo, g_Thi, pfx0, s3);
    const uint32_t kr = K_SEL - g_cntAbove;    // needed from the window

    uint4 h = ((const uint4*)g_h2)[t];          // coalesced: 4 bins/thread
    uint32_t hb[4] = {h.x, h.y, h.z, h.w};
    uint32_t part = hb[0] + hb[1] + hb[2] + hb[3];
    sscan[t] = part;
    __syncthreads();
    for (int off = 1; off < TPB; off <<= 1) {   // inclusive suffix scan
        uint32_t v = (t + off < TPB) ? sscan[t + off] : 0u;
        __syncthreads();
        sscan[t] += v;
        __syncthreads();
    }
    uint32_t tail = sscan[t] - part;            // count in chunks above t
    {
        uint32_t C = tail;
        for (int j = 3; j >= 0; j--) {          // bins high -> low
            uint32_t hh = hb[j];
            if (C < kr && C + hh >= kr) { s_B = (uint32_t)(t * 4 + j); s_need = kr - C; }
            C += hh;
        }
    }
    __syncthreads();
    const uint32_t B = s_B, need = s_need;

    // Contributions: full bins above B at midpoint, plus `need` elements at B.
    double ds = 0.0;
#pragma unroll
    for (int j = 0; j < 4; j++) {
        uint32_t idx = (uint32_t)(t * 4 + j);
        uint32_t hh = hb[j];
        if ((idx > B && hh) || idx == B) {
            uint32_t bits = (((pfx0 << 12) | idx) << s3) |
                            (s3 ? (1u << (s3 - 1)) : 0u);   // bin midpoint
            double m = (double)__uint_as_float(bits);
            ds += (idx > B) ? (double)hh * m : (double)need * m;
        }
    }
    const uint32_t lane = t & 31u;
#pragma unroll
    for (int o = 16; o; o >>= 1) ds += __shfl_down_sync(FULL, ds, o);
    if (lane == 0) dp[t >> 5] = ds;
    __syncthreads();
    if (t == 0) {
        double tot = g_sum;
#pragma unroll
        for (int i = 0; i < 32; i++) tot += dp[i];
        out[0] = (float)(tot / (double)K_SEL);
    }
    __syncthreads();
    // Re-zero remaining state for the next graph replay.
    for (int i = t; i < HBINS; i += TPB) g_hist[i] = 0u;
    if (t == 0) { g_sum = 0.0; g_cntAbove = 0u; }
}

// ---------------------------------------------------------------------------
extern "C" void kernel_launch(void* const* d_in, const int* in_sizes, int n_in,
                              void* d_out, int out_size) {
    (void)in_sizes; (void)n_in; (void)out_size;
    const float* pred = (const float*)d_in[0];
    const float* tgt  = (const float*)d_in[1];
    float* out = (float*)d_out;

    ksample<<<S_BLOCKS, TPB>>>(pred, tgt);
    kmain<<<GRID_BIG, TPB>>>(pred, tgt);
    kfin<<<1, TPB>>>(out);
}